// round 2
// baseline (speedup 1.0000x reference)
#include <cuda_runtime.h>
#include <cuda_fp16.h>
#include <cstdint>

#define D_MODEL 1024
#define D_FF    8192
#define N_ELEM  64
#define D1      128
#define BATCH   2048

// fp16 scratch: w1 transposed to (j, e, d) contiguous-d; w2 kept (e, j, d) contiguous-d.
__device__ __align__(16) __half g_w1t[(size_t)D_FF * D_MODEL];
__device__ __align__(16) __half g_w2h[(size_t)D_FF * D_MODEL];

// ---------------------------------------------------------------------------
// Kernel 1: transpose+convert w1 (d, j, e) fp32  ->  g_w1t[(j*64+e)*1024 + d] fp16
// Plain 1024 x 8192 transpose, tiled through smem. Coalesced reads, 16B writes.
// ---------------------------------------------------------------------------
__global__ __launch_bounds__(256) void transpose_w1_kernel(const float* __restrict__ w1) {
    __shared__ float tile[32][65];   // 32 d-rows x 64 je-cols (+1 pad, conflict-free)
    const int d0  = blockIdx.x * 32;
    const int je0 = blockIdx.y * 64;
    const int t   = threadIdx.x;

    const int dr = t >> 5;           // 0..7
    const int c  = (t & 31) * 2;     // 0..62
#pragma unroll
    for (int r = 0; r < 32; r += 8) {
        float2 v = *reinterpret_cast<const float2*>(
            w1 + (size_t)(d0 + r + dr) * D_FF + je0 + c);
        tile[r + dr][c]     = v.x;
        tile[r + dr][c + 1] = v.y;
    }
    __syncthreads();

    const int jl = t >> 2;           // 0..63  (je within tile)
    const int ds = (t & 3) * 8;      // 0,8,16,24 (d within tile)
    __half tmp[8];
#pragma unroll
    for (int i = 0; i < 8; i++) tmp[i] = __float2half_rn(tile[ds + i][jl]);
    *reinterpret_cast<uint4*>(g_w1t + (size_t)(je0 + jl) * D_MODEL + d0 + ds) =
        *reinterpret_cast<const uint4*>(tmp);
}

// ---------------------------------------------------------------------------
// Kernel 2: elementwise convert w2 fp32 -> fp16 (layout already gather-friendly)
// ---------------------------------------------------------------------------
__global__ __launch_bounds__(256) void convert_w2_kernel(const float* __restrict__ w2) {
    const size_t i = ((size_t)blockIdx.x * 256 + threadIdx.x) * 8;
    float4 a = *reinterpret_cast<const float4*>(w2 + i);
    float4 b = *reinterpret_cast<const float4*>(w2 + i + 4);
    __half tmp[8];
    tmp[0] = __float2half_rn(a.x); tmp[1] = __float2half_rn(a.y);
    tmp[2] = __float2half_rn(a.z); tmp[3] = __float2half_rn(a.w);
    tmp[4] = __float2half_rn(b.x); tmp[5] = __float2half_rn(b.y);
    tmp[6] = __float2half_rn(b.z); tmp[7] = __float2half_rn(b.w);
    *reinterpret_cast<uint4*>(g_w2h + i) = *reinterpret_cast<const uint4*>(tmp);
}

// ---------------------------------------------------------------------------
// Kernel 3: main fused sparse-FF. One CTA per sample (256 threads = 8 warps).
// Phase A: each warp computes mid for 16 blocks j via coalesced fp16 gather +
//          shuffle reduce -> relu(mid) in smem.
// Phase B: each warp owns a 128-float slice of res; loops all 128 j with a
//          warp-uniform relu broadcast; skips j when relu == 0 (~50%).
// ---------------------------------------------------------------------------
__global__ __launch_bounds__(256) void sparse_ff_kernel(
    const int*   __restrict__ qmask,
    const float* __restrict__ x,
    const float* __restrict__ b2,
    float*       __restrict__ out_res,
    float*       __restrict__ out_mask)   // may be null
{
    __shared__ float x_s[D_MODEL];
    __shared__ float midr[D1];
    __shared__ int   ms[D1];

    const int b = blockIdx.x;
    const int t = threadIdx.x;
    const int w = t >> 5;
    const int l = t & 31;

    // load x row (4KB) and mask row
    reinterpret_cast<float4*>(x_s)[t] =
        reinterpret_cast<const float4*>(x + (size_t)b * D_MODEL)[t];
    if (t < D1) {
        int m = qmask[(size_t)b * D1 + t];
        ms[t] = m;
        if (out_mask) out_mask[(size_t)b * D1 + t] = (float)m;
    }
    __syncthreads();

    // ---- Phase A: mid[j] = x . w1t[j, m_j, :] ----
#pragma unroll
    for (int jj = 0; jj < 16; jj++) {
        const int j = w + jj * 8;
        const int m = ms[j];
        const __half* wc = g_w1t + ((size_t)j * N_ELEM + m) * D_MODEL;
        float s = 0.f;
#pragma unroll
        for (int k = 0; k < 8; k++) {
            const int off = k * 128 + l * 4;
            uint2 hv = *reinterpret_cast<const uint2*>(wc + off);
            __half2 h0 = *reinterpret_cast<const __half2*>(&hv.x);
            __half2 h1 = *reinterpret_cast<const __half2*>(&hv.y);
            float2 f0 = __half22float2(h0);
            float2 f1 = __half22float2(h1);
            float4 xv = *reinterpret_cast<const float4*>(x_s + off);
            s = fmaf(f0.x, xv.x, s);
            s = fmaf(f0.y, xv.y, s);
            s = fmaf(f1.x, xv.z, s);
            s = fmaf(f1.y, xv.w, s);
        }
#pragma unroll
        for (int o = 16; o > 0; o >>= 1)
            s += __shfl_xor_sync(0xffffffffu, s, o);
        if (l == 0) midr[j] = fmaxf(s, 0.f);
    }
    __syncthreads();

    // ---- Phase B: res slice accumulation ----
    const int base = w * 128 + l * 4;
    float a0 = 0.f, a1 = 0.f, a2 = 0.f, a3 = 0.f;
#pragma unroll 4
    for (int j = 0; j < D1; j++) {
        const float r = midr[j];
        if (r > 0.f) {                       // warp-uniform branch
            const int m = ms[j];
            uint2 hv = *reinterpret_cast<const uint2*>(
                g_w2h + ((size_t)m * D1 + j) * D_MODEL + base);
            __half2 h0 = *reinterpret_cast<const __half2*>(&hv.x);
            __half2 h1 = *reinterpret_cast<const __half2*>(&hv.y);
            float2 f0 = __half22float2(h0);
            float2 f1 = __half22float2(h1);
            a0 = fmaf(r, f0.x, a0);
            a1 = fmaf(r, f0.y, a1);
            a2 = fmaf(r, f1.x, a2);
            a3 = fmaf(r, f1.y, a3);
        }
    }

    float4 bv = reinterpret_cast<const float4*>(b2)[base >> 2];
    float4 o;
    o.x = a0 + bv.x; o.y = a1 + bv.y; o.z = a2 + bv.z; o.w = a3 + bv.w;
    reinterpret_cast<float4*>(out_res + (size_t)b * D_MODEL)[base >> 2] = o;
}

// ---------------------------------------------------------------------------
extern "C" void kernel_launch(void* const* d_in, const int* in_sizes, int n_in,
                              void* d_out, int out_size) {
    // Identify inputs robustly by element count (dict order: qmask, x, w1, w2, b2)
    const int*   qmask = nullptr;
    const float* x = nullptr, *w1 = nullptr, *w2 = nullptr, *b2 = nullptr;
    for (int i = 0; i < n_in; i++) {
        const int sz = in_sizes[i];
        if (sz == BATCH * D1)            qmask = (const int*)d_in[i];
        else if (sz == BATCH * D_MODEL)  x     = (const float*)d_in[i];
        else if (sz == D_MODEL)          b2    = (const float*)d_in[i];
        else if (sz == D_MODEL * D_FF) {
            if (!w1) w1 = (const float*)d_in[i];
            else     w2 = (const float*)d_in[i];
        }
    }

    float* out      = (float*)d_out;
    float* out_mask = nullptr;
    float* out_res  = out;
    // Reference returns (quant_mask, res); if the harness concatenates both,
    // out_size covers mask + res, mask first.
    if (out_size >= BATCH * D1 + BATCH * D_MODEL) {
        out_mask = out;
        out_res  = out + BATCH * D1;
    }

    transpose_w1_kernel<<<dim3(D_MODEL / 32, D_FF / 64), 256>>>(w1);
    convert_w2_kernel<<<(D_FF * D_MODEL) / (256 * 8), 256>>>(w2);
    sparse_ff_kernel<<<BATCH, 256>>>(qmask, x, b2, out_res, out_mask);
}